// round 1
// baseline (speedup 1.0000x reference)
#include <cuda_runtime.h>
#include <cstring>

#define Bn 512
#define Tn 512
#define Nn 64

__device__ __forceinline__ unsigned long long fma2(unsigned long long a,
                                                   unsigned long long b,
                                                   unsigned long long c) {
    unsigned long long d;
    asm("fma.rn.f32x2 %0, %1, %2, %3;" : "=l"(d) : "l"(a), "l"(b), "l"(c));
    return d;
}

__device__ __forceinline__ unsigned long long pack2(float x, float y) {
    float2 f; f.x = x; f.y = y;
    unsigned long long u;
    memcpy(&u, &f, 8);
    return u;
}

__global__ void __launch_bounds__(64) crf_kernel(
    const float* __restrict__ inp,    // [B,T,N]
    const float* __restrict__ trans,  // [N,N]
    const int*   __restrict__ tags,   // [B,T]
    const int*   __restrict__ lens,   // [B]
    float*       __restrict__ out)    // [512 (+4096)]
{
    const int b = blockIdx.x;
    const int j = threadIdx.x;

    if (b >= Bn) {
        // transition_params copy (second output leaf)
        int idx = (b - Bn) * Nn + j;
        out[Bn + idx] = trans[idx];
        return;
    }

    __shared__ float pbuf[2][Nn];
    __shared__ float nslot[2];
    __shared__ float red[Nn];

    const int L    = lens[b];
    const int last = (L - 1) > 0 ? (L - 1) : 0;
    const long baseBT = (long)b * Tn;
    const float* __restrict__ erow = inp + baseBT * Nn;

    // ---------------- sequence score (parallel over t) ----------------
    float s = 0.f;
    for (int t = j; t < Tn; t += Nn) {
        if (t < L) {
            int tg = tags[baseBT + t];
            s += erow[t * Nn + tg];
            if (t >= 1) {
                int tp = tags[baseBT + t - 1];
                s += trans[tp * Nn + tg];
            }
        }
    }
    #pragma unroll
    for (int o = 16; o > 0; o >>= 1)
        s += __shfl_down_sync(0xffffffffu, s, o);
    if ((j & 31) == 0) red[j >> 5] = s;
    __syncthreads();
    const float seqscore = red[0] + red[1];   // valid in all threads
    __syncthreads();

    // ---------------- load E column j = exp(trans[:, j]) packed f32x2 ----------------
    unsigned long long E2[Nn / 2];
    #pragma unroll
    for (int i = 0; i < Nn / 2; i++) {
        float e0 = __expf(trans[(2 * i)     * Nn + j]);
        float e1 = __expf(trans[(2 * i + 1) * Nn + j]);
        E2[i] = pack2(e0, e1);
    }

    // ---------------- forward recursion ----------------
    float alpha = erow[j];          // alpha(0)_j
    float n = 0.f;                  // lagged normalizer
    // 2-deep emission prefetch (rows 1,2 always in-bounds: T=512)
    float e1v = erow[Nn * 1 + j];
    float e2v = erow[Nn * 2 + j];

    int buf = 0;
    for (int t = 1; t <= last; t++) {
        float p = __expf(alpha - n);
        pbuf[buf][j] = p;
        if (j == 0) nslot[buf] = alpha;   // normalizer for iteration t+1
        __syncthreads();

        const float nn = nslot[buf];
        const float emit = e1v;
        e1v = e2v;
        {
            int tn2 = t + 2; if (tn2 > Tn - 1) tn2 = Tn - 1;
            e2v = erow[tn2 * Nn + j];     // prefetch
        }

        const float4* p4 = reinterpret_cast<const float4*>(pbuf[buf]);
        unsigned long long acc0 = 0ull, acc1 = 0ull;   // (0.f, 0.f)
        #pragma unroll
        for (int i = 0; i < 16; i++) {
            float4 pv = p4[i];
            unsigned long long plo = pack2(pv.x, pv.y);
            unsigned long long phi = pack2(pv.z, pv.w);
            acc0 = fma2(plo, E2[2 * i],     acc0);
            acc1 = fma2(phi, E2[2 * i + 1], acc1);
        }
        float2 a0, a1;
        memcpy(&a0, &acc0, 8);
        memcpy(&a1, &acc1, 8);
        const float S = (a0.x + a0.y) + (a1.x + a1.y);

        alpha = emit + __logf(S) + n;
        n = nn;
        buf ^= 1;
    }

    // ---------------- final logsumexp over tags ----------------
    __syncthreads();          // protect red[] reuse
    red[j] = alpha;
    __syncthreads();
    if (j == 0) {
        float m = red[0];
        #pragma unroll
        for (int i = 1; i < Nn; i++) m = fmaxf(m, red[i]);
        float ss = 0.f;
        #pragma unroll
        for (int i = 0; i < Nn; i++) ss += __expf(red[i] - m);
        const float lognorm = m + __logf(ss);
        out[b] = seqscore - lognorm;
    }
}

extern "C" void kernel_launch(void* const* d_in, const int* in_sizes, int n_in,
                              void* d_out, int out_size) {
    const float* inp   = (const float*)d_in[0];
    const float* trans = (const float*)d_in[1];
    const int*   tags  = (const int*)d_in[2];
    const int*   lens  = (const int*)d_in[3];
    float* out = (float*)d_out;

    int nblocks = Bn;
    if (out_size >= Bn + Nn * Nn) nblocks += Nn;   // 64 copy blocks for transition_params
    crf_kernel<<<nblocks, Nn>>>(inp, trans, tags, lens, out);
}

// round 2
// speedup vs baseline: 1.3778x; 1.3778x over previous
#include <cuda_runtime.h>
#include <cstring>

#define Bn 512
#define Tn 512
#define Nn 64

__device__ __forceinline__ unsigned long long fma2(unsigned long long a,
                                                   unsigned long long b,
                                                   unsigned long long c) {
    unsigned long long d;
    asm("fma.rn.f32x2 %0, %1, %2, %3;" : "=l"(d) : "l"(a), "l"(b), "l"(c));
    return d;
}

__device__ __forceinline__ unsigned long long pack2(float x, float y) {
    float2 f; f.x = x; f.y = y;
    unsigned long long u;
    memcpy(&u, &f, 8);
    return u;
}

__global__ void __launch_bounds__(64) crf_kernel(
    const float* __restrict__ inp,    // [B,T,N]
    const float* __restrict__ trans,  // [N,N]
    const int*   __restrict__ tags,   // [B,T]
    const int*   __restrict__ lens,   // [B]
    float*       __restrict__ out)    // [512 (+4096)]
{
    const int b = blockIdx.x;
    const int j = threadIdx.x;

    if (b >= Bn) {
        int idx = (b - Bn) * Nn + j;
        out[Bn + idx] = trans[idx];
        return;
    }

    __shared__ float pbuf[2][Nn];
    __shared__ float nslot[2];
    __shared__ float red[Nn];

    const int L    = lens[b];
    const int last = (L - 1) > 0 ? (L - 1) : 0;
    const long baseBT = (long)b * Tn;
    const float* __restrict__ erow = inp + baseBT * Nn;

    // ---------------- sequence score (parallel over t) ----------------
    float s = 0.f;
    for (int t = j; t < Tn; t += Nn) {
        if (t < L) {
            int tg = tags[baseBT + t];
            s += erow[t * Nn + tg];
            if (t >= 1) {
                int tp = tags[baseBT + t - 1];
                s += trans[tp * Nn + tg];
            }
        }
    }
    #pragma unroll
    for (int o = 16; o > 0; o >>= 1)
        s += __shfl_down_sync(0xffffffffu, s, o);
    if ((j & 31) == 0) red[j >> 5] = s;
    __syncthreads();
    const float seqscore = red[0] + red[1];
    __syncthreads();

    // ---------------- E column j = exp(trans[:, j]) packed f32x2 ----------------
    unsigned long long E2[Nn / 2];
    #pragma unroll
    for (int i = 0; i < Nn / 2; i++) {
        float e0 = __expf(trans[(2 * i)     * Nn + j]);
        float e1 = __expf(trans[(2 * i + 1) * Nn + j]);
        E2[i] = pack2(e0, e1);
    }

    // ---------------- forward recursion ----------------
    float alpha = erow[j];          // alpha(0)_j
    float nrm = 0.f;                // lagged normalizer
    int buf = 0;

    // one recursion step, emission value EMIT (register)
#define STEP(EMIT)                                                        \
    do {                                                                  \
        float p = __expf(alpha - nrm);                                    \
        pbuf[buf][j] = p;                                                 \
        if (j == 0) nslot[buf] = alpha;                                   \
        __syncthreads();                                                  \
        const float nn = nslot[buf];                                      \
        const float4* p4 = reinterpret_cast<const float4*>(pbuf[buf]);    \
        unsigned long long a0 = 0ull, a1 = 0ull, a2 = 0ull, a3 = 0ull;    \
        _Pragma("unroll")                                                 \
        for (int i = 0; i < 8; i++) {                                     \
            float4 pv = p4[2 * i];                                        \
            float4 pw = p4[2 * i + 1];                                    \
            a0 = fma2(pack2(pv.x, pv.y), E2[4 * i + 0], a0);              \
            a1 = fma2(pack2(pv.z, pv.w), E2[4 * i + 1], a1);              \
            a2 = fma2(pack2(pw.x, pw.y), E2[4 * i + 2], a2);              \
            a3 = fma2(pack2(pw.z, pw.w), E2[4 * i + 3], a3);              \
        }                                                                 \
        float2 f0, f1, f2, f3;                                            \
        memcpy(&f0, &a0, 8); memcpy(&f1, &a1, 8);                         \
        memcpy(&f2, &a2, 8); memcpy(&f3, &a3, 8);                         \
        const float S = ((f0.x + f0.y) + (f1.x + f1.y)) +                 \
                        ((f2.x + f2.y) + (f3.x + f3.y));                  \
        alpha = (EMIT) + __logf(S) + nrm;                                 \
        nrm = nn;                                                         \
        buf ^= 1;                                                         \
    } while (0)

    // clamped emission row load for tag j
#define EMLOAD(ROW) erow[(((ROW) < Tn - 1) ? (ROW) : (Tn - 1)) * Nn + j]

    // current chunk regs (rows t..t+3), preloaded rows 1..4
    float c0 = EMLOAD(1), c1 = EMLOAD(2), c2 = EMLOAD(3), c3 = EMLOAD(4);

    int t = 1;
    for (; t + 3 <= last; t += 4) {
        // issue next chunk's 4 independent loads (hidden behind this chunk)
        float n0 = EMLOAD(t + 4);
        float n1 = EMLOAD(t + 5);
        float n2 = EMLOAD(t + 6);
        float n3 = EMLOAD(t + 7);
        STEP(c0);
        STEP(c1);
        STEP(c2);
        STEP(c3);
        c0 = n0; c1 = n1; c2 = n2; c3 = n3;
    }
    // tail: at most 3 steps; c0..c2 hold rows t..t+2
    if (t <= last) { STEP(c0); t++; }
    if (t <= last) { STEP(c1); t++; }
    if (t <= last) { STEP(c2); t++; }

#undef STEP
#undef EMLOAD

    // ---------------- final logsumexp over tags ----------------
    __syncthreads();
    red[j] = alpha;
    __syncthreads();
    if (j == 0) {
        float m = red[0];
        #pragma unroll
        for (int i = 1; i < Nn; i++) m = fmaxf(m, red[i]);
        float ss = 0.f;
        #pragma unroll
        for (int i = 0; i < Nn; i++) ss += __expf(red[i] - m);
        const float lognorm = m + __logf(ss);
        out[b] = seqscore - lognorm;
    }
}

extern "C" void kernel_launch(void* const* d_in, const int* in_sizes, int n_in,
                              void* d_out, int out_size) {
    const float* inp   = (const float*)d_in[0];
    const float* trans = (const float*)d_in[1];
    const int*   tags  = (const int*)d_in[2];
    const int*   lens  = (const int*)d_in[3];
    float* out = (float*)d_out;

    int nblocks = Bn;
    if (out_size >= Bn + Nn * Nn) nblocks += Nn;
    crf_kernel<<<nblocks, Nn>>>(inp, trans, tags, lens, out);
}